// round 12
// baseline (speedup 1.0000x reference)
#include <cuda_runtime.h>
#include <cuda_bf16.h>
#include <cuda_fp16.h>
#include <cstdint>

// ---------------------------------------------------------------------------
// Problem constants
// ---------------------------------------------------------------------------
#define BATCH 32768
#define TT    276
#define KDIM  4416       // T * 2H
#define NDIM  276        // output cols
#define NPAD  288        // padded N (multiple of 96)

// FC GEMM tiling
#define BM   128
#define BN   96
#define KC   64
#define NCH  69          // KDIM / KC
#define NSTAGE 4

#define A_OFF         0
#define B_OFF         16384
#define ST_BYTES      28672
#define SMEM_TOTAL    (NSTAGE * ST_BYTES)   // 114688

// ---------------------------------------------------------------------------
// Global scratch (static __device__ arrays: allocation-free)
// ---------------------------------------------------------------------------
__device__ __align__(128) __half   g_A16[(size_t)BATCH * KDIM];
__device__ __align__(128) __half   g_Wh[(size_t)NPAD * KDIM];
__device__ __align__(128) uint32_t g_Xv[(size_t)TT * BATCH * 4];  // [t][b][q]

// ---------------------------------------------------------------------------
// PTX helpers (sm_80-era ISA only: valid under plain sm_103 target)
// ---------------------------------------------------------------------------
__device__ __forceinline__ uint32_t smem_u32(const void* p) {
    uint32_t a;
    asm("{ .reg .u64 t; cvta.to.shared.u64 t, %1; cvt.u32.u64 %0, t; }"
        : "=r"(a) : "l"(p));
    return a;
}
__device__ __forceinline__ void cp16(uint32_t dst, const void* src) {
    asm volatile("cp.async.cg.shared.global [%0], [%1], 16;\n" :: "r"(dst), "l"(src));
}
__device__ __forceinline__ void cp_commit() {
    asm volatile("cp.async.commit_group;\n" ::: "memory");
}
template <int N>
__device__ __forceinline__ void cp_wait() {
    asm volatile("cp.async.wait_group %0;\n" :: "n"(N) : "memory");
}
__device__ __forceinline__ void ldsm_x4(uint32_t& r0, uint32_t& r1,
                                        uint32_t& r2, uint32_t& r3, uint32_t addr) {
    asm volatile("ldmatrix.sync.aligned.m8n8.x4.shared.b16 {%0,%1,%2,%3}, [%4];"
                 : "=r"(r0), "=r"(r1), "=r"(r2), "=r"(r3) : "r"(addr));
}
__device__ __forceinline__ void mma16816h(float* d, const uint32_t* a,
                                          const uint32_t* b) {
    asm volatile(
        "mma.sync.aligned.m16n8k16.row.col.f32.f16.f16.f32 "
        "{%0,%1,%2,%3}, {%4,%5,%6,%7}, {%8,%9}, {%0,%1,%2,%3};"
        : "+f"(d[0]), "+f"(d[1]), "+f"(d[2]), "+f"(d[3])
        : "r"(a[0]), "r"(a[1]), "r"(a[2]), "r"(a[3]), "r"(b[0]), "r"(b[1]));
}
// first-MMA variant: C = broadcast zero register (no per-step d zero-init)
__device__ __forceinline__ void mma16816h_z(float* d, const uint32_t* a,
                                            const uint32_t* b, float z) {
    asm volatile(
        "mma.sync.aligned.m16n8k16.row.col.f32.f16.f16.f32 "
        "{%0,%1,%2,%3}, {%4,%5,%6,%7}, {%8,%9}, {%10,%10,%10,%10};"
        : "=f"(d[0]), "=f"(d[1]), "=f"(d[2]), "=f"(d[3])
        : "r"(a[0]), "r"(a[1]), "r"(a[2]), "r"(a[3]), "r"(b[0]), "r"(b[1]),
          "f"(z));
}
__device__ __forceinline__ uint32_t sw128(uint32_t off) {
    return off ^ ((off >> 3) & 0x70);
}
__device__ __forceinline__ float tanh_hw(float x) {
    float y;
    asm("tanh.approx.f32 %0, %1;" : "=f"(y) : "f"(x));
    return y;
}
__device__ __forceinline__ uint32_t packh(__half a, __half b) {
    return (uint32_t)__half_as_ushort(a) | ((uint32_t)__half_as_ushort(b) << 16);
}

// ---------------------------------------------------------------------------
// Prep: Wfc -> fp16, zero-pad rows 276..287
// ---------------------------------------------------------------------------
__global__ void prep_kernel(const float* __restrict__ Wfc) {
    size_t idx = (size_t)blockIdx.x * blockDim.x + threadIdx.x;
    if (idx >= (size_t)NPAD * KDIM) return;
    int n = (int)(idx / KDIM);
    float v = (n < NDIM) ? Wfc[idx] : 0.0f;
    g_Wh[idx] = __float2half_rn(v);
}

// ---------------------------------------------------------------------------
// xprep: precompute per-(b,t) xvec quads, transposed to [t][b][q] layout.
// q0=(x0h,x0l) q1=(x1h,x1l) q2=(x0h,x1h) q3=(1,1).
// 16x16 (b,t) tile per block via smem so both read and write coalesce.
// ---------------------------------------------------------------------------
__global__ void __launch_bounds__(256) xprep_kernel(const float* __restrict__ x) {
    __shared__ uint4 tile[16][17];
    int bt = blockIdx.x;             // b-tile
    int tt = blockIdx.y;             // t-tile
    int tx = threadIdx.x & 15;       // t within tile (read phase)
    int ty = threadIdx.x >> 4;       // b within tile (read phase)
    int b = bt * 16 + ty;
    int t = tt * 16 + tx;
    if (t < TT) {
        float2 v = __ldg((const float2*)(x + ((size_t)b * TT + t) * 2));
        __half x0h = __float2half_rn(v.x);
        __half x1h = __float2half_rn(v.y);
        uint32_t q0 = packh(x0h, __float2half_rn(v.x - __half2float(x0h)));
        uint32_t q1 = packh(x1h, __float2half_rn(v.y - __half2float(x1h)));
        uint32_t q2 = packh(x0h, x1h);
        tile[tx][ty] = make_uint4(q0, q1, q2, 0x3C003C00u);
    }
    __syncthreads();
    int tb  = threadIdx.x & 15;      // b within tile (write phase)
    int ttw = threadIdx.x >> 4;      // t within tile (write phase)
    int tw = tt * 16 + ttw;
    if (tw < TT) {
        int bw = bt * 16 + tb;
        *(uint4*)(g_Xv + ((size_t)tw * BATCH + bw) * 4) = tile[ttw][tb];
    }
}

// ---------------------------------------------------------------------------
// Tensor-core LSTM, one m16 tile per warp; x-projection folded into MMA2's
// k8-15 slots via precomputed g_Xv:
//   MMA1: [h_hi|h_lo] @ [Whh_hi;Whh_hi]  (C = zero reg)
//   MMA2: [h_hi|xvec] @ [Whh_lo;Wx]
// ---------------------------------------------------------------------------
__global__ void __launch_bounds__(128, 7) lstm_kernel(
    const float* __restrict__ Wih_f, const float* __restrict__ Whh_f,
    const float* __restrict__ bih_f, const float* __restrict__ bhh_f,
    const float* __restrict__ Wih_b, const float* __restrict__ Whh_b,
    const float* __restrict__ bih_b, const float* __restrict__ bhh_b)
{
    int gw   = (blockIdx.x * blockDim.x + threadIdx.x) >> 5;  // 0..4095
    int lane = threadIdx.x & 31;
    int dir  = gw >> 11;
    int wb   = (gw & 2047) * 16;

    const float* Wih = dir ? Wih_b : Wih_f;
    const float* Whh = dir ? Whh_b : Whh_f;
    const float* bih = dir ? bih_b : bih_f;
    const float* bhh = dir ? bhh_b : bhh_f;

    int gn = lane >> 2;
    int u0 = (lane & 3) * 2;

    uint32_t whhHi[4], whhLo[4], bx[4];
#pragma unroll
    for (int nt = 0; nt < 4; nt++) {
        float s = (nt == 2) ? 1.0f : 0.5f;
        float w0 = Whh[(8 * nt + gn) * 8 + u0]     * s;
        float w1 = Whh[(8 * nt + gn) * 8 + u0 + 1] * s;
        __half h0 = __float2half_rn(w0);
        __half h1 = __float2half_rn(w1);
        whhHi[nt] = packh(h0, h1);
        whhLo[nt] = packh(__float2half_rn(w0 - __half2float(h0)),
                          __float2half_rn(w1 - __half2float(h1)));

        int g = 8 * nt + gn;
        float v0 = Wih[g * 2 + 0] * s;
        float v1 = Wih[g * 2 + 1] * s;
        float bb = (bih[g] + bhh[g]) * s;
        __half w0h = __float2half_rn(v0);
        __half w1h = __float2half_rn(v1);
        __half w0l = __float2half_rn(v0 - __half2float(w0h));
        __half w1l = __float2half_rn(v1 - __half2float(w1h));
        __half bh_ = __float2half_rn(bb);
        __half bl_ = __float2half_rn(bb - __half2float(bh_));
        uint32_t bv;
        if      (u0 == 0) bv = packh(w0h, w0h);
        else if (u0 == 2) bv = packh(w1h, w1h);
        else if (u0 == 4) bv = packh(w0l, w1l);
        else              bv = packh(bh_, bl_);
        bx[nt] = bv;
    }

    int t0 = dir ? (TT - 1) : 0;
    const uint32_t* xvp[2];
    uint32_t oidx[2];
#pragma unroll
    for (int sl = 0; sl < 2; sl++) {
        int b = wb + (lane >> 2) + 8 * sl;
        xvp[sl] = g_Xv + ((size_t)t0 * BATCH + b) * 4 + (lane & 3);
        oidx[sl] = (uint32_t)b * KDIM + dir * 8 + u0 + (uint32_t)t0 * 16;
    }
    int xstep = dir ? -(BATCH * 4) : (BATCH * 4);
    int ostep = dir ? -16 : 16;

    float cst[2][2] = {{0.f, 0.f}, {0.f, 0.f}};
    uint32_t aF[4] = {0u, 0u, 0u, 0u};
    float zf = 0.0f;

    uint32_t xq[2];
#pragma unroll
    for (int sl = 0; sl < 2; sl++) xq[sl] = __ldg(xvp[sl]);

    uint32_t stash[2], stashIdx[2];

#pragma unroll 2
    for (int step = 0; step < TT; step++) {
        uint32_t xv0 = xq[0], xv1 = xq[1];

        // prefetch next xvec
        if (step + 1 < TT) {
#pragma unroll
            for (int sl = 0; sl < 2; sl++) {
                xvp[sl] += xstep;
                xq[sl] = __ldg(xvp[sl]);
            }
        }

        // gates = h@Whh_hi + h_hi@Whh_lo + xproj + bias
        float d[4][4];
#pragma unroll
        for (int nt = 0; nt < 4; nt++) {
            uint32_t b1[2] = { whhHi[nt], whhHi[nt] };
            mma16816h_z(d[nt], aF, b1, zf);
            uint32_t a2[4] = { aF[0], aF[1], xv0, xv1 };
            uint32_t b2[2] = { whhLo[nt], bx[nt] };
            mma16816h(d[nt], a2, b2);
        }

        // activation + state update + repack (all in-lane)
#pragma unroll
        for (int sl = 0; sl < 2; sl++) {
            __half hh[2], hl[2];
#pragma unroll
            for (int cc = 0; cc < 2; cc++) {
                int di = sl * 2 + cc;
                float ig = fmaf(0.5f, tanh_hw(d[0][di]), 0.5f);
                float fg = fmaf(0.5f, tanh_hw(d[1][di]), 0.5f);
                float gg = tanh_hw(d[2][di]);
                float og = fmaf(0.5f, tanh_hw(d[3][di]), 0.5f);
                float cn = fmaf(fg, cst[sl][cc], ig * gg);
                cst[sl][cc] = cn;
                float hv = og * tanh_hw(cn);
                hh[cc] = __float2half_rn(hv);
                hl[cc] = __float2half_rn(hv - __half2float(hh[cc]));
            }
            uint32_t phi = packh(hh[0], hh[1]);
            aF[sl]     = phi;
            aF[2 + sl] = packh(hl[0], hl[1]);

            if ((step & 1) == 0) {
                stash[sl] = phi;
                stashIdx[sl] = oidx[sl];
            } else {
                *(uint32_t*)(g_A16 + stashIdx[sl]) = stash[sl];
                *(uint32_t*)(g_A16 + oidx[sl]) = phi;
            }
            oidx[sl] += ostep;
        }
    }
}

// ---------------------------------------------------------------------------
// FC GEMM via mma.sync (HMMA fp16, fp32 accum): out = A16*Wh^T + bias
// ---------------------------------------------------------------------------
extern __shared__ char dynsmem[];

__device__ __forceinline__ void load_chunk(int tid, int m0, int n0, uint32_t sb,
                                           int k, int s)
{
    uint32_t stb = sb + (uint32_t)s * ST_BYTES;
    size_t koff = (size_t)k * KC;
#pragma unroll
    for (int i = 0; i < 4; i++) {               // A: 128 rows x 8 x 16B
        int lin = tid + i * 256;
        int r = lin >> 3, cs = lin & 7;
        size_t src = (size_t)(m0 + r) * KDIM + koff + cs * 8;
        uint32_t sw = sw128((uint32_t)(r * 128 + cs * 16));
        cp16(stb + A_OFF + sw, g_A16 + src);
    }
#pragma unroll
    for (int i = 0; i < 3; i++) {               // B: 96 rows x 8 x 16B
        int lin = tid + i * 256;
        int r = lin >> 3, cs = lin & 7;
        size_t src = (size_t)(n0 + r) * KDIM + koff + cs * 8;
        uint32_t sw = sw128((uint32_t)(r * 128 + cs * 16));
        cp16(stb + B_OFF + sw, g_Wh + src);
    }
}

__global__ void __launch_bounds__(256, 2) fc_kernel(
    const float* __restrict__ bfc, float* __restrict__ out)
{
    uint32_t sb = smem_u32(dynsmem);
    int tid  = threadIdx.x;
    int lane = tid & 31;
    int warp = tid >> 5;
    int wm = warp & 3;
    int wn = warp >> 2;
    int n0 = blockIdx.x * BN;
    int m0 = blockIdx.y * BM;

    int arow = wm * 32 + (lane & 15);
    uint32_t a_x0 = ((uint32_t)arow & 7) << 4;
    uint32_t a_r0 = (uint32_t)arow * 128;
    int arow1 = arow + 16;
    uint32_t a_x1 = ((uint32_t)arow1 & 7) << 4;
    uint32_t a_r1 = (uint32_t)arow1 * 128;
    uint32_t a_half = ((uint32_t)(lane >> 4)) * 16;

    int bq = ((lane >> 4) & 1) * 8 + (lane & 7);
    uint32_t b_half = (((uint32_t)lane >> 3) & 1) * 16;

    float acc[2][6][4];
#pragma unroll
    for (int f = 0; f < 2; f++)
#pragma unroll
        for (int j = 0; j < 6; j++)
#pragma unroll
            for (int q = 0; q < 4; q++) acc[f][j][q] = 0.0f;

    load_chunk(tid, m0, n0, sb, 0, 0); cp_commit();
    load_chunk(tid, m0, n0, sb, 1, 1); cp_commit();
    load_chunk(tid, m0, n0, sb, 2, 2); cp_commit();

    for (int k = 0; k < NCH; k++) {
        cp_wait<2>();
        __syncthreads();
        if (k + 3 < NCH) load_chunk(tid, m0, n0, sb, k + 3, (k + 3) & 3);
        cp_commit();

        uint32_t stb = sb + (uint32_t)(k & 3) * ST_BYTES;
#pragma unroll
        for (int ks = 0; ks < 4; ks++) {
            uint32_t intraA = (uint32_t)ks * 32 + a_half;
            uint32_t ah[2][4];
            {
                uint32_t ad0 = stb + A_OFF + a_r0 + (intraA ^ a_x0);
                uint32_t ad1 = stb + A_OFF + a_r1 + (intraA ^ a_x1);
                ldsm_x4(ah[0][0], ah[0][1], ah[0][2], ah[0][3], ad0);
                ldsm_x4(ah[1][0], ah[1][1], ah[1][2], ah[1][3], ad1);
            }
            uint32_t bh[6][2];
#pragma unroll
            for (int t = 0; t < 3; t++) {
                int brow = wn * 48 + t * 16 + bq;
                uint32_t b_r = (uint32_t)brow * 128;
                uint32_t b_x = ((uint32_t)brow & 7) << 4;
                uint32_t intraB = (uint32_t)ks * 32 + b_half;
                uint32_t adH = stb + B_OFF + b_r + (intraB ^ b_x);
                ldsm_x4(bh[t*2][0], bh[t*2][1], bh[t*2+1][0], bh[t*2+1][1], adH);
            }
#pragma unroll
            for (int f = 0; f < 2; f++)
#pragma unroll
                for (int j = 0; j < 6; j++)
                    mma16816h(acc[f][j], ah[f], bh[j]);
        }
    }

    int g  = lane >> 2;
    int tg = lane & 3;
#pragma unroll
    for (int f = 0; f < 2; f++) {
        int row0 = m0 + wm * 32 + f * 16 + g;
#pragma unroll
        for (int j = 0; j < 6; j++) {
            int col = n0 + wn * 48 + j * 8 + tg * 2;
            if (col < NDIM) {
                float b0 = __ldg(&bfc[col]), b1 = __ldg(&bfc[col + 1]);
                float2 v0 = make_float2(acc[f][j][0] + b0, acc[f][j][1] + b1);
                float2 v1 = make_float2(acc[f][j][2] + b0, acc[f][j][3] + b1);
                *(float2*)(out + (size_t)row0 * NDIM + col) = v0;
                *(float2*)(out + (size_t)(row0 + 8) * NDIM + col) = v1;
            }
        }
    }
}

// ---------------------------------------------------------------------------

extern "C" void kernel_launch(void* const* d_in, const int* in_sizes, int n_in,
                              void* d_out, int out_size)
{
    const float* x     = (const float*)d_in[0];
    const float* Wih_f = (const float*)d_in[1];
    const float* Whh_f = (const float*)d_in[2];
    const float* bih_f = (const float*)d_in[3];
    const float* bhh_f = (const float*)d_in[4];
    const float* Wih_b = (const float*)d_in[5];
    const float* Whh_b = (const float*)d_in[6];
    const float* bih_b = (const float*)d_in[7];
    const float* bhh_b = (const float*)d_in[8];
    const float* Wfc   = (const float*)d_in[9];
    const float* bfc   = (const float*)d_in[10];
    float* out = (float*)d_out;

    cudaFuncSetAttribute(fc_kernel, cudaFuncAttributeMaxDynamicSharedMemorySize,
                         SMEM_TOTAL);

    dim3 xg(BATCH / 16, (TT + 15) / 16);
    xprep_kernel<<<xg, 256>>>(x);
    lstm_kernel<<<1024, 128>>>(Wih_f, Whh_f, bih_f, bhh_f,
                               Wih_b, Whh_b, bih_b, bhh_b);
    prep_kernel<<<(NPAD * KDIM) / 256, 256>>>(Wfc);
    dim3 grid(3, BATCH / BM);
    fc_kernel<<<grid, 256, SMEM_TOTAL>>>(bfc, out);
}

// round 13
// speedup vs baseline: 1.0586x; 1.0586x over previous
#include <cuda_runtime.h>
#include <cuda_bf16.h>
#include <cuda_fp16.h>
#include <cstdint>

// ---------------------------------------------------------------------------
// Problem constants
// ---------------------------------------------------------------------------
#define BATCH 32768
#define TT    276
#define KDIM  4416       // T * 2H
#define NDIM  276        // output cols
#define NPAD  288        // padded N (multiple of 96)

// FC GEMM tiling
#define BM   128
#define BN   96
#define KC   64
#define NCH  69          // KDIM / KC
#define NSTAGE 4

#define A_OFF         0
#define B_OFF         16384
#define ST_BYTES      28672
#define SMEM_TOTAL    (NSTAGE * ST_BYTES)   // 114688

// ---------------------------------------------------------------------------
// Global scratch (static __device__ arrays: allocation-free)
// ---------------------------------------------------------------------------
__device__ __align__(128) __half   g_A16[(size_t)BATCH * KDIM];
__device__ __align__(128) __half   g_Wh[(size_t)NPAD * KDIM];
__device__ __align__(128) uint32_t g_Xv[(size_t)TT * BATCH * 4];  // [t][b][q]

// ---------------------------------------------------------------------------
// PTX helpers (sm_80-era ISA only: valid under plain sm_103 target)
// ---------------------------------------------------------------------------
__device__ __forceinline__ uint32_t smem_u32(const void* p) {
    uint32_t a;
    asm("{ .reg .u64 t; cvta.to.shared.u64 t, %1; cvt.u32.u64 %0, t; }"
        : "=r"(a) : "l"(p));
    return a;
}
__device__ __forceinline__ void cp16(uint32_t dst, const void* src) {
    asm volatile("cp.async.cg.shared.global [%0], [%1], 16;\n" :: "r"(dst), "l"(src));
}
__device__ __forceinline__ void cp_commit() {
    asm volatile("cp.async.commit_group;\n" ::: "memory");
}
template <int N>
__device__ __forceinline__ void cp_wait() {
    asm volatile("cp.async.wait_group %0;\n" :: "n"(N) : "memory");
}
__device__ __forceinline__ void ldsm_x4(uint32_t& r0, uint32_t& r1,
                                        uint32_t& r2, uint32_t& r3, uint32_t addr) {
    asm volatile("ldmatrix.sync.aligned.m8n8.x4.shared.b16 {%0,%1,%2,%3}, [%4];"
                 : "=r"(r0), "=r"(r1), "=r"(r2), "=r"(r3) : "r"(addr));
}
__device__ __forceinline__ void mma16816h(float* d, const uint32_t* a,
                                          const uint32_t* b) {
    asm volatile(
        "mma.sync.aligned.m16n8k16.row.col.f32.f16.f16.f32 "
        "{%0,%1,%2,%3}, {%4,%5,%6,%7}, {%8,%9}, {%0,%1,%2,%3};"
        : "+f"(d[0]), "+f"(d[1]), "+f"(d[2]), "+f"(d[3])
        : "r"(a[0]), "r"(a[1]), "r"(a[2]), "r"(a[3]), "r"(b[0]), "r"(b[1]));
}
__device__ __forceinline__ void mma16816h_z(float* d, const uint32_t* a,
                                            const uint32_t* b, float z) {
    asm volatile(
        "mma.sync.aligned.m16n8k16.row.col.f32.f16.f16.f32 "
        "{%0,%1,%2,%3}, {%4,%5,%6,%7}, {%8,%9}, {%10,%10,%10,%10};"
        : "=f"(d[0]), "=f"(d[1]), "=f"(d[2]), "=f"(d[3])
        : "r"(a[0]), "r"(a[1]), "r"(a[2]), "r"(a[3]), "r"(b[0]), "r"(b[1]),
          "f"(z));
}
__device__ __forceinline__ uint32_t sw128(uint32_t off) {
    return off ^ ((off >> 3) & 0x70);
}
__device__ __forceinline__ float tanh_hw(float x) {
    float y;
    asm("tanh.approx.f32 %0, %1;" : "=f"(y) : "f"(x));
    return y;
}
__device__ __forceinline__ uint32_t packh(__half a, __half b) {
    return (uint32_t)__half_as_ushort(a) | ((uint32_t)__half_as_ushort(b) << 16);
}

// ---------------------------------------------------------------------------
// Prep: Wfc -> fp16, zero-pad rows 276..287
// ---------------------------------------------------------------------------
__global__ void prep_kernel(const float* __restrict__ Wfc) {
    size_t idx = (size_t)blockIdx.x * blockDim.x + threadIdx.x;
    if (idx >= (size_t)NPAD * KDIM) return;
    int n = (int)(idx / KDIM);
    float v = (n < NDIM) ? Wfc[idx] : 0.0f;
    g_Wh[idx] = __float2half_rn(v);
}

// ---------------------------------------------------------------------------
// xprep: precompute per-(b,t) xvec quads, transposed to [t][b][q] layout.
// ---------------------------------------------------------------------------
__global__ void __launch_bounds__(256) xprep_kernel(const float* __restrict__ x) {
    __shared__ uint4 tile[16][17];
    int bt = blockIdx.x;
    int tt = blockIdx.y;
    int tx = threadIdx.x & 15;
    int ty = threadIdx.x >> 4;
    int b = bt * 16 + ty;
    int t = tt * 16 + tx;
    if (t < TT) {
        float2 v = __ldg((const float2*)(x + ((size_t)b * TT + t) * 2));
        __half x0h = __float2half_rn(v.x);
        __half x1h = __float2half_rn(v.y);
        uint32_t q0 = packh(x0h, __float2half_rn(v.x - __half2float(x0h)));
        uint32_t q1 = packh(x1h, __float2half_rn(v.y - __half2float(x1h)));
        uint32_t q2 = packh(x0h, x1h);
        tile[tx][ty] = make_uint4(q0, q1, q2, 0x3C003C00u);
    }
    __syncthreads();
    int tb  = threadIdx.x & 15;
    int ttw = threadIdx.x >> 4;
    int tw = tt * 16 + ttw;
    if (tw < TT) {
        int bw = bt * 16 + tb;
        *(uint4*)(g_Xv + ((size_t)tw * BATCH + bw) * 4) = tile[ttw][tb];
    }
}

// ---------------------------------------------------------------------------
// Tensor-core LSTM, one m16 tile per warp; x-projection folded into MMA2.
// ---------------------------------------------------------------------------
__global__ void __launch_bounds__(128, 7) lstm_kernel(
    const float* __restrict__ Wih_f, const float* __restrict__ Whh_f,
    const float* __restrict__ bih_f, const float* __restrict__ bhh_f,
    const float* __restrict__ Wih_b, const float* __restrict__ Whh_b,
    const float* __restrict__ bih_b, const float* __restrict__ bhh_b)
{
    int gw   = (blockIdx.x * blockDim.x + threadIdx.x) >> 5;
    int lane = threadIdx.x & 31;
    int dir  = gw >> 11;
    int wb   = (gw & 2047) * 16;

    const float* Wih = dir ? Wih_b : Wih_f;
    const float* Whh = dir ? Whh_b : Whh_f;
    const float* bih = dir ? bih_b : bih_f;
    const float* bhh = dir ? bhh_b : bhh_f;

    int gn = lane >> 2;
    int u0 = (lane & 3) * 2;

    uint32_t whhHi[4], whhLo[4], bx[4];
#pragma unroll
    for (int nt = 0; nt < 4; nt++) {
        float s = (nt == 2) ? 1.0f : 0.5f;
        float w0 = Whh[(8 * nt + gn) * 8 + u0]     * s;
        float w1 = Whh[(8 * nt + gn) * 8 + u0 + 1] * s;
        __half h0 = __float2half_rn(w0);
        __half h1 = __float2half_rn(w1);
        whhHi[nt] = packh(h0, h1);
        whhLo[nt] = packh(__float2half_rn(w0 - __half2float(h0)),
                          __float2half_rn(w1 - __half2float(h1)));

        int g = 8 * nt + gn;
        float v0 = Wih[g * 2 + 0] * s;
        float v1 = Wih[g * 2 + 1] * s;
        float bb = (bih[g] + bhh[g]) * s;
        __half w0h = __float2half_rn(v0);
        __half w1h = __float2half_rn(v1);
        __half w0l = __float2half_rn(v0 - __half2float(w0h));
        __half w1l = __float2half_rn(v1 - __half2float(w1h));
        __half bh_ = __float2half_rn(bb);
        __half bl_ = __float2half_rn(bb - __half2float(bh_));
        uint32_t bv;
        if      (u0 == 0) bv = packh(w0h, w0h);
        else if (u0 == 2) bv = packh(w1h, w1h);
        else if (u0 == 4) bv = packh(w0l, w1l);
        else              bv = packh(bh_, bl_);
        bx[nt] = bv;
    }

    int t0 = dir ? (TT - 1) : 0;
    const uint32_t* xvp[2];
    uint32_t oidx[2];
#pragma unroll
    for (int sl = 0; sl < 2; sl++) {
        int b = wb + (lane >> 2) + 8 * sl;
        xvp[sl] = g_Xv + ((size_t)t0 * BATCH + b) * 4 + (lane & 3);
        oidx[sl] = (uint32_t)b * KDIM + dir * 8 + u0 + (uint32_t)t0 * 16;
    }
    int xstep = dir ? -(BATCH * 4) : (BATCH * 4);
    int ostep = dir ? -16 : 16;

    float cst[2][2] = {{0.f, 0.f}, {0.f, 0.f}};
    uint32_t aF[4] = {0u, 0u, 0u, 0u};
    float zf = 0.0f;

    uint32_t xq[2];
#pragma unroll
    for (int sl = 0; sl < 2; sl++) xq[sl] = __ldg(xvp[sl]);

    uint32_t stash[2], stashIdx[2];

#pragma unroll 2
    for (int step = 0; step < TT; step++) {
        uint32_t xv0 = xq[0], xv1 = xq[1];

        if (step + 1 < TT) {
#pragma unroll
            for (int sl = 0; sl < 2; sl++) {
                xvp[sl] += xstep;
                xq[sl] = __ldg(xvp[sl]);
            }
        }

        float d[4][4];
#pragma unroll
        for (int nt = 0; nt < 4; nt++) {
            uint32_t b1[2] = { whhHi[nt], whhHi[nt] };
            mma16816h_z(d[nt], aF, b1, zf);
            uint32_t a2[4] = { aF[0], aF[1], xv0, xv1 };
            uint32_t b2[2] = { whhLo[nt], bx[nt] };
            mma16816h(d[nt], a2, b2);
        }

#pragma unroll
        for (int sl = 0; sl < 2; sl++) {
            float hv[2];
#pragma unroll
            for (int cc = 0; cc < 2; cc++) {
                int di = sl * 2 + cc;
                float ig = fmaf(0.5f, tanh_hw(d[0][di]), 0.5f);
                float fg = fmaf(0.5f, tanh_hw(d[1][di]), 0.5f);
                float gg = tanh_hw(d[2][di]);
                float og = fmaf(0.5f, tanh_hw(d[3][di]), 0.5f);
                float cn = fmaf(fg, cst[sl][cc], ig * gg);
                cst[sl][cc] = cn;
                hv[cc] = og * tanh_hw(cn);
            }
            // packed f16x2 conversions (same rn rounding as scalar path)
            __half2 H = __floats2half2_rn(hv[0], hv[1]);
            uint32_t phi = *reinterpret_cast<uint32_t*>(&H);
            float2 hf = __half22float2(H);
            __half2 L = __floats2half2_rn(hv[0] - hf.x, hv[1] - hf.y);
            aF[sl]     = phi;
            aF[2 + sl] = *reinterpret_cast<uint32_t*>(&L);

            if ((step & 1) == 0) {
                stash[sl] = phi;
                stashIdx[sl] = oidx[sl];
            } else {
                *(uint32_t*)(g_A16 + stashIdx[sl]) = stash[sl];
                *(uint32_t*)(g_A16 + oidx[sl]) = phi;
            }
            oidx[sl] += ostep;
        }
    }
}

// ---------------------------------------------------------------------------
// FC GEMM via mma.sync (HMMA fp16, fp32 accum): out = A16*Wh^T + bias
// Fragment double-buffered: ldsm for ks+1 issues before MMAs of ks.
// ---------------------------------------------------------------------------
extern __shared__ char dynsmem[];

struct Frag {
    uint32_t a[2][4];
    uint32_t b[6][2];
};

__device__ __forceinline__ void load_frags(
    uint32_t stb, int ks, Frag& F,
    uint32_t a_r0, uint32_t a_x0, uint32_t a_r1, uint32_t a_x1,
    uint32_t a_half, int wn, int bq, uint32_t b_half)
{
    uint32_t intraA = (uint32_t)ks * 32 + a_half;
    ldsm_x4(F.a[0][0], F.a[0][1], F.a[0][2], F.a[0][3],
            stb + A_OFF + a_r0 + (intraA ^ a_x0));
    ldsm_x4(F.a[1][0], F.a[1][1], F.a[1][2], F.a[1][3],
            stb + A_OFF + a_r1 + (intraA ^ a_x1));
#pragma unroll
    for (int t = 0; t < 3; t++) {
        int brow = wn * 48 + t * 16 + bq;
        uint32_t b_r = (uint32_t)brow * 128;
        uint32_t b_x = ((uint32_t)brow & 7) << 4;
        uint32_t intraB = (uint32_t)ks * 32 + b_half;
        ldsm_x4(F.b[t*2][0], F.b[t*2][1], F.b[t*2+1][0], F.b[t*2+1][1],
                stb + B_OFF + b_r + (intraB ^ b_x));
    }
}

__device__ __forceinline__ void load_chunk(int tid, int m0, int n0, uint32_t sb,
                                           int k, int s)
{
    uint32_t stb = sb + (uint32_t)s * ST_BYTES;
    size_t koff = (size_t)k * KC;
#pragma unroll
    for (int i = 0; i < 4; i++) {               // A: 128 rows x 8 x 16B
        int lin = tid + i * 256;
        int r = lin >> 3, cs = lin & 7;
        size_t src = (size_t)(m0 + r) * KDIM + koff + cs * 8;
        uint32_t sw = sw128((uint32_t)(r * 128 + cs * 16));
        cp16(stb + A_OFF + sw, g_A16 + src);
    }
#pragma unroll
    for (int i = 0; i < 3; i++) {               // B: 96 rows x 8 x 16B
        int lin = tid + i * 256;
        int r = lin >> 3, cs = lin & 7;
        size_t src = (size_t)(n0 + r) * KDIM + koff + cs * 8;
        uint32_t sw = sw128((uint32_t)(r * 128 + cs * 16));
        cp16(stb + B_OFF + sw, g_Wh + src);
    }
}

__global__ void __launch_bounds__(256, 2) fc_kernel(
    const float* __restrict__ bfc, float* __restrict__ out)
{
    uint32_t sb = smem_u32(dynsmem);
    int tid  = threadIdx.x;
    int lane = tid & 31;
    int warp = tid >> 5;
    int wm = warp & 3;
    int wn = warp >> 2;
    int n0 = blockIdx.x * BN;
    int m0 = blockIdx.y * BM;

    int arow = wm * 32 + (lane & 15);
    uint32_t a_x0 = ((uint32_t)arow & 7) << 4;
    uint32_t a_r0 = (uint32_t)arow * 128;
    int arow1 = arow + 16;
    uint32_t a_x1 = ((uint32_t)arow1 & 7) << 4;
    uint32_t a_r1 = (uint32_t)arow1 * 128;
    uint32_t a_half = ((uint32_t)(lane >> 4)) * 16;

    int bq = ((lane >> 4) & 1) * 8 + (lane & 7);
    uint32_t b_half = (((uint32_t)lane >> 3) & 1) * 16;

    float acc[2][6][4];
#pragma unroll
    for (int f = 0; f < 2; f++)
#pragma unroll
        for (int j = 0; j < 6; j++)
#pragma unroll
            for (int q = 0; q < 4; q++) acc[f][j][q] = 0.0f;

    load_chunk(tid, m0, n0, sb, 0, 0); cp_commit();
    load_chunk(tid, m0, n0, sb, 1, 1); cp_commit();
    load_chunk(tid, m0, n0, sb, 2, 2); cp_commit();

    Frag fr[2];
    cp_wait<1>();           // chunks 0 and 1 complete
    __syncthreads();        // publish
    load_frags(sb, 0, fr[0], a_r0, a_x0, a_r1, a_x1, a_half, wn, bq, b_half);

    for (int k = 0; k < NCH; k++) {
        if (k > 0) {
            cp_wait<1>();   // chunks <= k+1 complete
            __syncthreads();
        }
        if (k + 3 < NCH) load_chunk(tid, m0, n0, sb, k + 3, (k + 3) & 3);
        cp_commit();

        uint32_t stb  = sb + (uint32_t)(k & 3) * ST_BYTES;
        uint32_t stbn = sb + (uint32_t)((k + 1) & 3) * ST_BYTES;
#pragma unroll
        for (int ks = 0; ks < 4; ks++) {
            Frag& cur = fr[ks & 1];
            Frag& nxt = fr[(ks + 1) & 1];
            if (ks < 3)
                load_frags(stb, ks + 1, nxt,
                           a_r0, a_x0, a_r1, a_x1, a_half, wn, bq, b_half);
            else if (k + 1 < NCH)
                load_frags(stbn, 0, nxt,
                           a_r0, a_x0, a_r1, a_x1, a_half, wn, bq, b_half);
#pragma unroll
            for (int f = 0; f < 2; f++)
#pragma unroll
                for (int j = 0; j < 6; j++)
                    mma16816h(acc[f][j], cur.a[f], cur.b[j]);
        }
    }

    int g  = lane >> 2;
    int tg = lane & 3;
#pragma unroll
    for (int f = 0; f < 2; f++) {
        int row0 = m0 + wm * 32 + f * 16 + g;
#pragma unroll
        for (int j = 0; j < 6; j++) {
            int col = n0 + wn * 48 + j * 8 + tg * 2;
            if (col < NDIM) {
                float b0 = __ldg(&bfc[col]), b1 = __ldg(&bfc[col + 1]);
                float2 v0 = make_float2(acc[f][j][0] + b0, acc[f][j][1] + b1);
                float2 v1 = make_float2(acc[f][j][2] + b0, acc[f][j][3] + b1);
                *(float2*)(out + (size_t)row0 * NDIM + col) = v0;
                *(float2*)(out + (size_t)(row0 + 8) * NDIM + col) = v1;
            }
        }
    }
}

// ---------------------------------------------------------------------------

extern "C" void kernel_launch(void* const* d_in, const int* in_sizes, int n_in,
                              void* d_out, int out_size)
{
    const float* x     = (const float*)d_in[0];
    const float* Wih_f = (const float*)d_in[1];
    const float* Whh_f = (const float*)d_in[2];
    const float* bih_f = (const float*)d_in[3];
    const float* bhh_f = (const float*)d_in[4];
    const float* Wih_b = (const float*)d_in[5];
    const float* Whh_b = (const float*)d_in[6];
    const float* bih_b = (const float*)d_in[7];
    const float* bhh_b = (const float*)d_in[8];
    const float* Wfc   = (const float*)d_in[9];
    const float* bfc   = (const float*)d_in[10];
    float* out = (float*)d_out;

    cudaFuncSetAttribute(fc_kernel, cudaFuncAttributeMaxDynamicSharedMemorySize,
                         SMEM_TOTAL);

    dim3 xg(BATCH / 16, (TT + 15) / 16);
    xprep_kernel<<<xg, 256>>>(x);
    lstm_kernel<<<1024, 128>>>(Wih_f, Whh_f, bih_f, bhh_f,
                               Wih_b, Whh_b, bih_b, bhh_b);
    prep_kernel<<<(NPAD * KDIM) / 256, 256>>>(Wfc);
    dim3 grid(3, BATCH / BM);
    fc_kernel<<<grid, 256, SMEM_TOTAL>>>(bfc, out);
}

// round 15
// speedup vs baseline: 1.1619x; 1.0975x over previous
#include <cuda_runtime.h>
#include <cuda_bf16.h>
#include <cuda_fp16.h>
#include <cstdint>

// ---------------------------------------------------------------------------
// Problem constants
// ---------------------------------------------------------------------------
#define BATCH 32768
#define TT    276
#define KDIM  4416       // T * 2H
#define NDIM  276        // output cols
#define NPAD  288        // padded N (multiple of 96)

// FC GEMM tiling
#define BM   128
#define BN   96
#define KC   64
#define NCH  69          // KDIM / KC
#define NSTAGE 4

#define A_OFF         0
#define B_OFF         16384
#define ST_BYTES      28672
#define SMEM_TOTAL    (NSTAGE * ST_BYTES)   // 114688

// ---------------------------------------------------------------------------
// Global scratch (static __device__ arrays: allocation-free)
// ---------------------------------------------------------------------------
__device__ __align__(128) __half   g_A16[(size_t)BATCH * KDIM];
__device__ __align__(128) __half   g_Wh[(size_t)NPAD * KDIM];
__device__ __align__(128) uint32_t g_Xv[(size_t)TT * BATCH * 4];  // [t][b][q]

// ---------------------------------------------------------------------------
// PTX helpers (sm_80-era ISA only: valid under plain sm_103 target)
// ---------------------------------------------------------------------------
__device__ __forceinline__ uint32_t smem_u32(const void* p) {
    uint32_t a;
    asm("{ .reg .u64 t; cvta.to.shared.u64 t, %1; cvt.u32.u64 %0, t; }"
        : "=r"(a) : "l"(p));
    return a;
}
__device__ __forceinline__ void cp16(uint32_t dst, const void* src) {
    asm volatile("cp.async.cg.shared.global [%0], [%1], 16;\n" :: "r"(dst), "l"(src));
}
__device__ __forceinline__ void cp_commit() {
    asm volatile("cp.async.commit_group;\n" ::: "memory");
}
template <int N>
__device__ __forceinline__ void cp_wait() {
    asm volatile("cp.async.wait_group %0;\n" :: "n"(N) : "memory");
}
__device__ __forceinline__ void ldsm_x4(uint32_t& r0, uint32_t& r1,
                                        uint32_t& r2, uint32_t& r3, uint32_t addr) {
    asm volatile("ldmatrix.sync.aligned.m8n8.x4.shared.b16 {%0,%1,%2,%3}, [%4];"
                 : "=r"(r0), "=r"(r1), "=r"(r2), "=r"(r3) : "r"(addr));
}
__device__ __forceinline__ void mma16816h(float* d, const uint32_t* a,
                                          const uint32_t* b) {
    asm volatile(
        "mma.sync.aligned.m16n8k16.row.col.f32.f16.f16.f32 "
        "{%0,%1,%2,%3}, {%4,%5,%6,%7}, {%8,%9}, {%0,%1,%2,%3};"
        : "+f"(d[0]), "+f"(d[1]), "+f"(d[2]), "+f"(d[3])
        : "r"(a[0]), "r"(a[1]), "r"(a[2]), "r"(a[3]), "r"(b[0]), "r"(b[1]));
}
// direct-operand variants: no array temps, operands are scalar registers
__device__ __forceinline__ void mma_z(
    float& d0, float& d1, float& d2, float& d3,
    uint32_t a0, uint32_t a1, uint32_t a2, uint32_t a3,
    uint32_t b0, uint32_t b1, float z)
{
    asm volatile(
        "mma.sync.aligned.m16n8k16.row.col.f32.f16.f16.f32 "
        "{%0,%1,%2,%3}, {%4,%5,%6,%7}, {%8,%9}, {%10,%10,%10,%10};"
        : "=f"(d0), "=f"(d1), "=f"(d2), "=f"(d3)
        : "r"(a0), "r"(a1), "r"(a2), "r"(a3), "r"(b0), "r"(b1), "f"(z));
}
__device__ __forceinline__ void mma_acc(
    float& d0, float& d1, float& d2, float& d3,
    uint32_t a0, uint32_t a1, uint32_t a2, uint32_t a3,
    uint32_t b0, uint32_t b1)
{
    asm volatile(
        "mma.sync.aligned.m16n8k16.row.col.f32.f16.f16.f32 "
        "{%0,%1,%2,%3}, {%4,%5,%6,%7}, {%8,%9}, {%0,%1,%2,%3};"
        : "+f"(d0), "+f"(d1), "+f"(d2), "+f"(d3)
        : "r"(a0), "r"(a1), "r"(a2), "r"(a3), "r"(b0), "r"(b1));
}
__device__ __forceinline__ uint32_t sw128(uint32_t off) {
    return off ^ ((off >> 3) & 0x70);
}
__device__ __forceinline__ float tanh_hw(float x) {
    float y;
    asm("tanh.approx.f32 %0, %1;" : "=f"(y) : "f"(x));
    return y;
}
__device__ __forceinline__ uint32_t packh(__half a, __half b) {
    return (uint32_t)__half_as_ushort(a) | ((uint32_t)__half_as_ushort(b) << 16);
}

// ---------------------------------------------------------------------------
// Prep: Wfc -> fp16, zero-pad rows 276..287
// ---------------------------------------------------------------------------
__global__ void prep_kernel(const float* __restrict__ Wfc) {
    size_t idx = (size_t)blockIdx.x * blockDim.x + threadIdx.x;
    if (idx >= (size_t)NPAD * KDIM) return;
    int n = (int)(idx / KDIM);
    float v = (n < NDIM) ? Wfc[idx] : 0.0f;
    g_Wh[idx] = __float2half_rn(v);
}

// ---------------------------------------------------------------------------
// xprep: precompute per-(b,t) xvec quads, transposed to [t][b][q] layout.
// ---------------------------------------------------------------------------
__global__ void __launch_bounds__(256) xprep_kernel(const float* __restrict__ x) {
    __shared__ uint4 tile[16][17];
    int bt = blockIdx.x;
    int tt = blockIdx.y;
    int tx = threadIdx.x & 15;
    int ty = threadIdx.x >> 4;
    int b = bt * 16 + ty;
    int t = tt * 16 + tx;
    if (t < TT) {
        float2 v = __ldg((const float2*)(x + ((size_t)b * TT + t) * 2));
        __half x0h = __float2half_rn(v.x);
        __half x1h = __float2half_rn(v.y);
        uint32_t q0 = packh(x0h, __float2half_rn(v.x - __half2float(x0h)));
        uint32_t q1 = packh(x1h, __float2half_rn(v.y - __half2float(x1h)));
        uint32_t q2 = packh(x0h, x1h);
        tile[tx][ty] = make_uint4(q0, q1, q2, 0x3C003C00u);
    }
    __syncthreads();
    int tb  = threadIdx.x & 15;
    int ttw = threadIdx.x >> 4;
    int tw = tt * 16 + ttw;
    if (tw < TT) {
        int bw = bt * 16 + tb;
        *(uint4*)(g_Xv + ((size_t)tw * BATCH + bw) * 4) = tile[ttw][tb];
    }
}

// ---------------------------------------------------------------------------
// Tensor-core LSTM, one m16 tile per warp; x-projection folded into MMA2.
// All 4 independent MMA1s issue first (4 HMMA chains in flight), then MMA2s.
// ---------------------------------------------------------------------------
__global__ void __launch_bounds__(128, 7) lstm_kernel(
    const float* __restrict__ Wih_f, const float* __restrict__ Whh_f,
    const float* __restrict__ bih_f, const float* __restrict__ bhh_f,
    const float* __restrict__ Wih_b, const float* __restrict__ Whh_b,
    const float* __restrict__ bih_b, const float* __restrict__ bhh_b)
{
    int gw   = (blockIdx.x * blockDim.x + threadIdx.x) >> 5;
    int lane = threadIdx.x & 31;
    int dir  = gw >> 11;
    int wb   = (gw & 2047) * 16;

    const float* Wih = dir ? Wih_b : Wih_f;
    const float* Whh = dir ? Whh_b : Whh_f;
    const float* bih = dir ? bih_b : bih_f;
    const float* bhh = dir ? bhh_b : bhh_f;

    int gn = lane >> 2;
    int u0 = (lane & 3) * 2;

    uint32_t whhHi[4], whhLo[4], bx[4];
#pragma unroll
    for (int nt = 0; nt < 4; nt++) {
        float s = (nt == 2) ? 1.0f : 0.5f;
        float w0 = Whh[(8 * nt + gn) * 8 + u0]     * s;
        float w1 = Whh[(8 * nt + gn) * 8 + u0 + 1] * s;
        __half h0 = __float2half_rn(w0);
        __half h1 = __float2half_rn(w1);
        whhHi[nt] = packh(h0, h1);
        whhLo[nt] = packh(__float2half_rn(w0 - __half2float(h0)),
                          __float2half_rn(w1 - __half2float(h1)));

        int g = 8 * nt + gn;
        float v0 = Wih[g * 2 + 0] * s;
        float v1 = Wih[g * 2 + 1] * s;
        float bb = (bih[g] + bhh[g]) * s;
        __half w0h = __float2half_rn(v0);
        __half w1h = __float2half_rn(v1);
        __half w0l = __float2half_rn(v0 - __half2float(w0h));
        __half w1l = __float2half_rn(v1 - __half2float(w1h));
        __half bh_ = __float2half_rn(bb);
        __half bl_ = __float2half_rn(bb - __half2float(bh_));
        uint32_t bv;
        if      (u0 == 0) bv = packh(w0h, w0h);
        else if (u0 == 2) bv = packh(w1h, w1h);
        else if (u0 == 4) bv = packh(w0l, w1l);
        else              bv = packh(bh_, bl_);
        bx[nt] = bv;
    }

    int t0 = dir ? (TT - 1) : 0;
    const uint32_t* xvp[2];
    uint32_t oidx[2];
#pragma unroll
    for (int sl = 0; sl < 2; sl++) {
        int b = wb + (lane >> 2) + 8 * sl;
        xvp[sl] = g_Xv + ((size_t)t0 * BATCH + b) * 4 + (lane & 3);
        oidx[sl] = (uint32_t)b * KDIM + dir * 8 + u0 + (uint32_t)t0 * 16;
    }
    int xstep = dir ? -(BATCH * 4) : (BATCH * 4);
    int ostep = dir ? -16 : 16;

    float cst[2][2] = {{0.f, 0.f}, {0.f, 0.f}};
    uint32_t aF0 = 0u, aF1 = 0u, aF2 = 0u, aF3 = 0u;
    float zf = 0.0f;

    uint32_t xq[2];
#pragma unroll
    for (int sl = 0; sl < 2; sl++) xq[sl] = __ldg(xvp[sl]);

    uint32_t stash[2], stashIdx[2];

#pragma unroll 4
    for (int step = 0; step < TT; step++) {
        uint32_t xv0 = xq[0], xv1 = xq[1];

        if (step + 1 < TT) {
#pragma unroll
            for (int sl = 0; sl < 2; sl++) {
                xvp[sl] += xstep;
                xq[sl] = __ldg(xvp[sl]);
            }
        }

        // 4 independent MMA1s first (h @ Whh_hi), then the dependent MMA2s
        float d[4][4];
        mma_z(d[0][0], d[0][1], d[0][2], d[0][3],
              aF0, aF1, aF2, aF3, whhHi[0], whhHi[0], zf);
        mma_z(d[1][0], d[1][1], d[1][2], d[1][3],
              aF0, aF1, aF2, aF3, whhHi[1], whhHi[1], zf);
        mma_z(d[2][0], d[2][1], d[2][2], d[2][3],
              aF0, aF1, aF2, aF3, whhHi[2], whhHi[2], zf);
        mma_z(d[3][0], d[3][1], d[3][2], d[3][3],
              aF0, aF1, aF2, aF3, whhHi[3], whhHi[3], zf);

        mma_acc(d[0][0], d[0][1], d[0][2], d[0][3],
                aF0, aF1, xv0, xv1, whhLo[0], bx[0]);
        mma_acc(d[1][0], d[1][1], d[1][2], d[1][3],
                aF0, aF1, xv0, xv1, whhLo[1], bx[1]);
        mma_acc(d[2][0], d[2][1], d[2][2], d[2][3],
                aF0, aF1, xv0, xv1, whhLo[2], bx[2]);
        mma_acc(d[3][0], d[3][1], d[3][2], d[3][3],
                aF0, aF1, xv0, xv1, whhLo[3], bx[3]);

#pragma unroll
        for (int sl = 0; sl < 2; sl++) {
            float hv[2];
#pragma unroll
            for (int cc = 0; cc < 2; cc++) {
                int di = sl * 2 + cc;
                float ig = fmaf(0.5f, tanh_hw(d[0][di]), 0.5f);
                float fg = fmaf(0.5f, tanh_hw(d[1][di]), 0.5f);
                float gg = tanh_hw(d[2][di]);
                float og = fmaf(0.5f, tanh_hw(d[3][di]), 0.5f);
                float cn = fmaf(fg, cst[sl][cc], ig * gg);
                cst[sl][cc] = cn;
                hv[cc] = og * tanh_hw(cn);
            }
            __half2 H = __floats2half2_rn(hv[0], hv[1]);
            uint32_t phi = *reinterpret_cast<uint32_t*>(&H);
            float2 hf = __half22float2(H);
            __half2 L = __floats2half2_rn(hv[0] - hf.x, hv[1] - hf.y);
            uint32_t plo = *reinterpret_cast<uint32_t*>(&L);
            if (sl == 0) { aF0 = phi; aF2 = plo; }
            else         { aF1 = phi; aF3 = plo; }

            if ((step & 1) == 0) {
                stash[sl] = phi;
                stashIdx[sl] = oidx[sl];
            } else {
                *(uint32_t*)(g_A16 + stashIdx[sl]) = stash[sl];
                *(uint32_t*)(g_A16 + oidx[sl]) = phi;
            }
            oidx[sl] += ostep;
        }
    }
}

// ---------------------------------------------------------------------------
// FC GEMM via mma.sync (HMMA fp16, fp32 accum): out = A16*Wh^T + bias
// Fragment double-buffered: ldsm for ks+1 issues before MMAs of ks.
// ---------------------------------------------------------------------------
extern __shared__ char dynsmem[];

struct Frag {
    uint32_t a[2][4];
    uint32_t b[6][2];
};

__device__ __forceinline__ void load_frags(
    uint32_t stb, int ks, Frag& F,
    uint32_t a_r0, uint32_t a_x0, uint32_t a_r1, uint32_t a_x1,
    uint32_t a_half, int wn, int bq, uint32_t b_half)
{
    uint32_t intraA = (uint32_t)ks * 32 + a_half;
    ldsm_x4(F.a[0][0], F.a[0][1], F.a[0][2], F.a[0][3],
            stb + A_OFF + a_r0 + (intraA ^ a_x0));
    ldsm_x4(F.a[1][0], F.a[1][1], F.a[1][2], F.a[1][3],
            stb + A_OFF + a_r1 + (intraA ^ a_x1));
#pragma unroll
    for (int t = 0; t < 3; t++) {
        int brow = wn * 48 + t * 16 + bq;
        uint32_t b_r = (uint32_t)brow * 128;
        uint32_t b_x = ((uint32_t)brow & 7) << 4;
        uint32_t intraB = (uint32_t)ks * 32 + b_half;
        ldsm_x4(F.b[t*2][0], F.b[t*2][1], F.b[t*2+1][0], F.b[t*2+1][1],
                stb + B_OFF + b_r + (intraB ^ b_x));
    }
}

__device__ __forceinline__ void load_chunk(int tid, int m0, int n0, uint32_t sb,
                                           int k, int s)
{
    uint32_t stb = sb + (uint32_t)s * ST_BYTES;
    size_t koff = (size_t)k * KC;
#pragma unroll
    for (int i = 0; i < 4; i++) {               // A: 128 rows x 8 x 16B
        int lin = tid + i * 256;
        int r = lin >> 3, cs = lin & 7;
        size_t src = (size_t)(m0 + r) * KDIM + koff + cs * 8;
        uint32_t sw = sw128((uint32_t)(r * 128 + cs * 16));
        cp16(stb + A_OFF + sw, g_A16 + src);
    }
#pragma unroll
    for (int i = 0; i < 3; i++) {               // B: 96 rows x 8 x 16B
        int lin = tid + i * 256;
        int r = lin >> 3, cs = lin & 7;
        size_t src = (size_t)(n0 + r) * KDIM + koff + cs * 8;
        uint32_t sw = sw128((uint32_t)(r * 128 + cs * 16));
        cp16(stb + B_OFF + sw, g_Wh + src);
    }
}

__global__ void __launch_bounds__(256, 2) fc_kernel(
    const float* __restrict__ bfc, float* __restrict__ out)
{
    uint32_t sb = smem_u32(dynsmem);
    int tid  = threadIdx.x;
    int lane = tid & 31;
    int warp = tid >> 5;
    int wm = warp & 3;
    int wn = warp >> 2;
    int n0 = blockIdx.x * BN;
    int m0 = blockIdx.y * BM;

    int arow = wm * 32 + (lane & 15);
    uint32_t a_x0 = ((uint32_t)arow & 7) << 4;
    uint32_t a_r0 = (uint32_t)arow * 128;
    int arow1 = arow + 16;
    uint32_t a_x1 = ((uint32_t)arow1 & 7) << 4;
    uint32_t a_r1 = (uint32_t)arow1 * 128;
    uint32_t a_half = ((uint32_t)(lane >> 4)) * 16;

    int bq = ((lane >> 4) & 1) * 8 + (lane & 7);
    uint32_t b_half = (((uint32_t)lane >> 3) & 1) * 16;

    float acc[2][6][4];
#pragma unroll
    for (int f = 0; f < 2; f++)
#pragma unroll
        for (int j = 0; j < 6; j++)
#pragma unroll
            for (int q = 0; q < 4; q++) acc[f][j][q] = 0.0f;

    load_chunk(tid, m0, n0, sb, 0, 0); cp_commit();
    load_chunk(tid, m0, n0, sb, 1, 1); cp_commit();
    load_chunk(tid, m0, n0, sb, 2, 2); cp_commit();

    Frag fr[2];
    cp_wait<1>();           // chunks 0 and 1 complete
    __syncthreads();        // publish
    load_frags(sb, 0, fr[0], a_r0, a_x0, a_r1, a_x1, a_half, wn, bq, b_half);

    for (int k = 0; k < NCH; k++) {
        if (k > 0) {
            cp_wait<1>();   // chunks <= k+1 complete
            __syncthreads();
        }
        if (k + 3 < NCH) load_chunk(tid, m0, n0, sb, k + 3, (k + 3) & 3);
        cp_commit();

        uint32_t stb  = sb + (uint32_t)(k & 3) * ST_BYTES;
        uint32_t stbn = sb + (uint32_t)((k + 1) & 3) * ST_BYTES;
#pragma unroll
        for (int ks = 0; ks < 4; ks++) {
            Frag& cur = fr[ks & 1];
            Frag& nxt = fr[(ks + 1) & 1];
            if (ks < 3)
                load_frags(stb, ks + 1, nxt,
                           a_r0, a_x0, a_r1, a_x1, a_half, wn, bq, b_half);
            else if (k + 1 < NCH)
                load_frags(stbn, 0, nxt,
                           a_r0, a_x0, a_r1, a_x1, a_half, wn, bq, b_half);
#pragma unroll
            for (int f = 0; f < 2; f++)
#pragma unroll
                for (int j = 0; j < 6; j++)
                    mma16816h(acc[f][j], cur.a[f], cur.b[j]);
        }
    }

    int g  = lane >> 2;
    int tg = lane & 3;
#pragma unroll
    for (int f = 0; f < 2; f++) {
        int row0 = m0 + wm * 32 + f * 16 + g;
#pragma unroll
        for (int j = 0; j < 6; j++) {
            int col = n0 + wn * 48 + j * 8 + tg * 2;
            if (col < NDIM) {
                float b0 = __ldg(&bfc[col]), b1 = __ldg(&bfc[col + 1]);
                float2 v0 = make_float2(acc[f][j][0] + b0, acc[f][j][1] + b1);
                float2 v1 = make_float2(acc[f][j][2] + b0, acc[f][j][3] + b1);
                *(float2*)(out + (size_t)row0 * NDIM + col) = v0;
                *(float2*)(out + (size_t)(row0 + 8) * NDIM + col) = v1;
            }
        }
    }
}

// ---------------------------------------------------------------------------

extern "C" void kernel_launch(void* const* d_in, const int* in_sizes, int n_in,
                              void* d_out, int out_size)
{
    const float* x     = (const float*)d_in[0];
    const float* Wih_f = (const float*)d_in[1];
    const float* Whh_f = (const float*)d_in[2];
    const float* bih_f = (const float*)d_in[3];
    const float* bhh_f = (const float*)d_in[4];
    const float* Wih_b = (const float*)d_in[5];
    const float* Whh_b = (const float*)d_in[6];
    const float* bih_b = (const float*)d_in[7];
    const float* bhh_b = (const float*)d_in[8];
    const float* Wfc   = (const float*)d_in[9];
    const float* bfc   = (const float*)d_in[10];
    float* out = (float*)d_out;

    cudaFuncSetAttribute(fc_kernel, cudaFuncAttributeMaxDynamicSharedMemorySize,
                         SMEM_TOTAL);

    dim3 xg(BATCH / 16, (TT + 15) / 16);
    xprep_kernel<<<xg, 256>>>(x);
    lstm_kernel<<<1024, 128>>>(Wih_f, Whh_f, bih_f, bhh_f,
                               Wih_b, Whh_b, bih_b, bhh_b);
    prep_kernel<<<(NPAD * KDIM) / 256, 256>>>(Wfc);
    dim3 grid(3, BATCH / BM);
    fc_kernel<<<grid, 256, SMEM_TOTAL>>>(bfc, out);
}